// round 2
// baseline (speedup 1.0000x reference)
#include <cuda_runtime.h>
#include <math.h>

#define NTOK 8192
#define DIM  1024
#define DLS  128
#define NE   8
#define NH   4
#define HDV  32
#define TT   2048
#define BBATCH 4
#define S9   9

// ---------------- scratch (device globals; no allocs allowed) ----------------
__device__ float g_ef[NTOK * DIM];      // expert_feats (N, E*DL)
__device__ float g_ahat[NTOK * DIM];    // coef * gelu(ef)
__device__ float g_xmean[BBATCH * DIM]; // sum over T (divide later)
__device__ float g_gctx[BBATCH * DLS];
__device__ float g_rq[BBATCH * DLS];
__device__ float g_probs[NTOK * NE];
__device__ float g_coef[NTOK * NE];
__device__ float g_wt_in[DLS * 384];    // attn_in_w transposed [d][j]
__device__ float g_wt_out[DLS * DLS];   // attn_out_w transposed
__device__ float g_wt_rk[DLS * DLS];    // rk_w transposed

__device__ __forceinline__ float gelu_f(float x) {
    return 0.5f * x * (1.0f + erff(x * 0.70710678118654752440f));
}

// ---------------- prep: zero accumulators + transpose small weights ----------
__global__ void k_prep(const float* __restrict__ aiw,
                       const float* __restrict__ aow,
                       const float* __restrict__ rkw) {
    int idx = blockIdx.x * blockDim.x + threadIdx.x;
    if (idx < BBATCH * DIM) g_xmean[idx] = 0.0f;
    if (idx < 384 * DLS) {
        int j = idx / DLS, d = idx % DLS;
        g_wt_in[d * 384 + j] = aiw[idx];
    } else if (idx < 384 * DLS + DLS * DLS) {
        int t = idx - 384 * DLS;
        int j = t / DLS, d = t % DLS;
        g_wt_out[d * DLS + j] = aow[t];
    } else if (idx < 384 * DLS + 2 * DLS * DLS) {
        int t = idx - 384 * DLS - DLS * DLS;
        int j = t / DLS, d = t % DLS;
        g_wt_rk[d * DLS + j] = rkw[t];
    }
}

// ---------------- column mean of x over T (partial sums via atomics) ---------
__global__ void k_colmean(const float* __restrict__ x) {
    int b = blockIdx.y, tc = blockIdx.x, tid = threadIdx.x;
    const float* xb = x + (size_t)b * TT * DIM + (size_t)tc * 128 * DIM;
    float acc[4] = {0.f, 0.f, 0.f, 0.f};
    for (int t = 0; t < 128; t++) {
        const float* row = xb + (size_t)t * DIM + tid;
#pragma unroll
        for (int i = 0; i < 4; i++) acc[i] += row[i * 256];
    }
#pragma unroll
    for (int i = 0; i < 4; i++)
        atomicAdd(&g_xmean[b * DIM + tid + i * 256], acc[i]);
}

// ---------------- block-wide sum over 128 threads ----------------------------
__device__ __forceinline__ float bsum128(float v, float* sred) {
    int tid = threadIdx.x;
#pragma unroll
    for (int o = 16; o > 0; o >>= 1) v += __shfl_down_sync(0xffffffffu, v, o);
    if ((tid & 31) == 0) sred[tid >> 5] = v;
    __syncthreads();
    float s = sred[0] + sred[1] + sred[2] + sred[3];
    __syncthreads();
    return s;
}

// ---------------- gctx + rq (per batch; grid=4, block=128) -------------------
__global__ void __launch_bounds__(128) k_gctx_rq(
    const float* __restrict__ gpw, const float* __restrict__ gpb,
    const float* __restrict__ rq1w, const float* __restrict__ rq1b,
    const float* __restrict__ rqlnw, const float* __restrict__ rqlnb,
    const float* __restrict__ rq2w, const float* __restrict__ rq2b) {
    __shared__ float sx[DIM];
    __shared__ float sg[DLS];
    __shared__ float sh[DLS];
    __shared__ float sred[4];
    int b = blockIdx.x, c = threadIdx.x;
    for (int i = c; i < DIM; i += 128) sx[i] = g_xmean[b * DIM + i] * (1.0f / TT);
    __syncthreads();

    // gctx[c] = sum_d xmean[d] * gpw[c][d] + gpb[c]
    float acc = 0.f;
    const float4* gw4 = (const float4*)(gpw + (size_t)c * DIM);
    const float4* sx4 = (const float4*)sx;
    for (int d4 = 0; d4 < DIM / 4; d4++) {
        float4 wv = gw4[d4], xv = sx4[d4];
        acc += wv.x * xv.x + wv.y * xv.y + wv.z * xv.z + wv.w * xv.w;
    }
    float gc = acc + gpb[c];
    g_gctx[b * DLS + c] = gc;
    sg[c] = gc;
    __syncthreads();

    // t = gctx @ rq1^T + b
    float t = 0.f;
    {
        const float4* w4 = (const float4*)(rq1w + (size_t)c * DLS);
        const float4* g4 = (const float4*)sg;
        for (int d4 = 0; d4 < DLS / 4; d4++) {
            float4 wv = w4[d4], xv = g4[d4];
            t += wv.x * xv.x + wv.y * xv.y + wv.z * xv.z + wv.w * xv.w;
        }
        t += rq1b[c];
    }
    // LN over 128
    float s = bsum128(t, sred);
    float q = bsum128(t * t, sred);
    float mu = s * (1.0f / 128.0f);
    float var = q * (1.0f / 128.0f) - mu * mu;
    float h = (t - mu) * rsqrtf(var + 1e-5f) * rqlnw[c] + rqlnb[c];
    h = gelu_f(h);
    sh[c] = h;
    __syncthreads();

    float r2 = 0.f;
    {
        const float4* w4 = (const float4*)(rq2w + (size_t)c * DLS);
        const float4* h4 = (const float4*)sh;
        for (int d4 = 0; d4 < DLS / 4; d4++) {
            float4 wv = w4[d4], xv = h4[d4];
            r2 += wv.x * xv.x + wv.y * xv.y + wv.z * xv.z + wv.w * xv.w;
        }
        r2 += rq2b[c];
    }
    g_rq[b * DLS + c] = r2;
}

// ---------------- tiled fp32 GEMM: C = A @ B^T (BT=1) or A @ B (BT=0) --------
template <bool BT>
__device__ __forceinline__ void gemm_dev(const float* __restrict__ A,
                                         const float* __restrict__ Bm,
                                         float* __restrict__ C,
                                         int M, int N, int Kd) {
    __shared__ __align__(16) float As[16][132];
    __shared__ __align__(16) float Bs[16][132];
    int tid = threadIdx.x;
    int tx = tid & 15, ty = tid >> 4;
    int n0 = blockIdx.x * 128, m0 = blockIdx.y * 128;
    float acc[8][8];
#pragma unroll
    for (int i = 0; i < 8; i++)
#pragma unroll
        for (int j = 0; j < 8; j++) acc[i][j] = 0.f;

    for (int k0 = 0; k0 < Kd; k0 += 16) {
#pragma unroll
        for (int i = 0; i < 8; i++) {
            int t = tid + i * 256;
            int r = t >> 4, k = t & 15;
            As[k][r] = A[(size_t)(m0 + r) * Kd + k0 + k];
        }
        if (BT) {
#pragma unroll
            for (int i = 0; i < 8; i++) {
                int t = tid + i * 256;
                int r = t >> 4, k = t & 15;
                Bs[k][r] = Bm[(size_t)(n0 + r) * Kd + k0 + k];
            }
        } else {
#pragma unroll
            for (int i = 0; i < 8; i++) {
                int t = tid + i * 256;
                int k = t >> 7, nn = t & 127;
                Bs[k][nn] = Bm[(size_t)(k0 + k) * N + n0 + nn];
            }
        }
        __syncthreads();
#pragma unroll
        for (int k = 0; k < 16; k++) {
            float4 a0 = *(const float4*)&As[k][ty * 8];
            float4 a1 = *(const float4*)&As[k][ty * 8 + 4];
            float4 b0 = *(const float4*)&Bs[k][tx * 8];
            float4 b1 = *(const float4*)&Bs[k][tx * 8 + 4];
            float av[8] = {a0.x, a0.y, a0.z, a0.w, a1.x, a1.y, a1.z, a1.w};
            float bv[8] = {b0.x, b0.y, b0.z, b0.w, b1.x, b1.y, b1.z, b1.w};
#pragma unroll
            for (int i = 0; i < 8; i++)
#pragma unroll
                for (int j = 0; j < 8; j++) acc[i][j] += av[i] * bv[j];
        }
        __syncthreads();
    }
#pragma unroll
    for (int i = 0; i < 8; i++) {
        float4 c0 = make_float4(acc[i][0], acc[i][1], acc[i][2], acc[i][3]);
        float4 c1 = make_float4(acc[i][4], acc[i][5], acc[i][6], acc[i][7]);
        size_t off = (size_t)(m0 + ty * 8 + i) * N + n0 + tx * 8;
        *(float4*)(C + off) = c0;
        *(float4*)(C + off + 4) = c1;
    }
}

__global__ void __launch_bounds__(256) k_gemm_ef(const float* __restrict__ A,
                                                const float* __restrict__ Bm) {
    gemm_dev<true>(A, Bm, g_ef, NTOK, DIM, DIM);
}
__global__ void __launch_bounds__(256) k_gemm_out(const float* __restrict__ Bm,
                                                 float* __restrict__ C) {
    gemm_dev<false>(g_ahat, Bm, C, NTOK, DIM, DIM);
}

// ---------------- per-token fused attention/router (grid=N, block=128) -------
__global__ void __launch_bounds__(128) k_token(
    const float* __restrict__ pos, const float* __restrict__ aib,
    const float* __restrict__ aob, const float* __restrict__ nw,
    const float* __restrict__ nb, const float* __restrict__ rkb) {
    __shared__ float s_seq[S9][DLS];
    __shared__ float s_qkv[S9][384];
    __shared__ float s_o[S9][DLS];
    __shared__ float s_s2[S9][DLS];
    __shared__ float s_red[NE][DLS];
    __shared__ float s_rq[DLS];
    __shared__ float s_mu[S9], s_rs[S9];
    __shared__ float s_logit[NE];
    __shared__ float s_coef[NE];

    int n = blockIdx.x;
    int b = n >> 11;  // T = 2048
    int c = threadIdx.x;
    int w = c >> 5, lane = c & 31;

    // build seq: row0 = gctx, rows 1..8 = ef + pos
    s_seq[0][c] = g_gctx[b * DLS + c];
#pragma unroll
    for (int e = 0; e < NE; e++)
        s_seq[1 + e][c] = g_ef[(size_t)n * DIM + e * DLS + c] + pos[e * DLS + c];
    s_rq[c] = g_rq[b * DLS + c];
    __syncthreads();

    // qkv = seq @ attn_in_w^T + b  (each thread owns cols c, c+128, c+256, all 9 rows)
    float acc0[S9], acc1[S9], acc2[S9];
#pragma unroll
    for (int r = 0; r < S9; r++) { acc0[r] = 0.f; acc1[r] = 0.f; acc2[r] = 0.f; }
    for (int d = 0; d < DLS; d++) {
        float w0 = g_wt_in[d * 384 + c];
        float w1 = g_wt_in[d * 384 + 128 + c];
        float w2 = g_wt_in[d * 384 + 256 + c];
#pragma unroll
        for (int r = 0; r < S9; r++) {
            float s = s_seq[r][d];
            acc0[r] += s * w0;
            acc1[r] += s * w1;
            acc2[r] += s * w2;
        }
    }
    {
        float b0 = aib[c], b1 = aib[128 + c], b2 = aib[256 + c];
#pragma unroll
        for (int r = 0; r < S9; r++) {
            s_qkv[r][c] = acc0[r] + b0;
            s_qkv[r][128 + c] = acc1[r] + b1;
            s_qkv[r][256 + c] = acc2[r] + b2;
        }
    }
    __syncthreads();

    // attention: warp w = head, lanes 0..8 = q rows
    if (lane < S9) {
        int h = w;
        const float scale = 0.17677669529663688f;  // 1/sqrt(32)
        float sc[S9];
#pragma unroll
        for (int j = 0; j < S9; j++) {
            float s = 0.f;
#pragma unroll
            for (int dd = 0; dd < HDV; dd++)
                s += s_qkv[lane][h * HDV + dd] * s_qkv[j][128 + h * HDV + dd];
            sc[j] = s * scale;
        }
        float m = sc[0];
#pragma unroll
        for (int j = 1; j < S9; j++) m = fmaxf(m, sc[j]);
        float ssum = 0.f;
#pragma unroll
        for (int j = 0; j < S9; j++) { sc[j] = expf(sc[j] - m); ssum += sc[j]; }
        float inv = 1.0f / ssum;
#pragma unroll
        for (int dd = 0; dd < HDV; dd++) {
            float o = 0.f;
#pragma unroll
            for (int j = 0; j < S9; j++) o += sc[j] * s_qkv[j][256 + h * HDV + dd];
            s_o[lane][h * HDV + dd] = o * inv;
        }
    }
    __syncthreads();

    // out proj + bias + residual
    {
        float po[S9];
#pragma unroll
        for (int r = 0; r < S9; r++) po[r] = 0.f;
        for (int d = 0; d < DLS; d++) {
            float wv = g_wt_out[d * DLS + c];
#pragma unroll
            for (int r = 0; r < S9; r++) po[r] += s_o[r][d] * wv;
        }
        float bo = aob[c];
#pragma unroll
        for (int r = 0; r < S9; r++) s_s2[r][c] = po[r] + bo + s_seq[r][c];
    }
    __syncthreads();

    // layernorm stats per row
    for (int r = w; r < S9; r += 4) {
        float v0 = s_s2[r][lane], v1 = s_s2[r][lane + 32];
        float v2 = s_s2[r][lane + 64], v3 = s_s2[r][lane + 96];
        float s = v0 + v1 + v2 + v3;
        float q = v0 * v0 + v1 * v1 + v2 * v2 + v3 * v3;
#pragma unroll
        for (int o = 16; o > 0; o >>= 1) {
            s += __shfl_down_sync(0xffffffffu, s, o);
            q += __shfl_down_sync(0xffffffffu, q, o);
        }
        if (lane == 0) {
            float mu = s * (1.0f / 128.0f);
            float var = q * (1.0f / 128.0f) - mu * mu;
            s_mu[r] = mu;
            s_rs[r] = rsqrtf(var + 1e-5f);
        }
    }
    __syncthreads();
    {
        float nwc = nw[c], nbc = nb[c];
#pragma unroll
        for (int r = 0; r < S9; r++) {
            float v = s_s2[r][c];
            s_s2[r][c] = (v - s_mu[r]) * s_rs[r] * nwc + nbc;
        }
    }
    __syncthreads();

    // rk = refined @ rk_w^T + b;  red[e][c] = rk[e][c] * rq[c]
    {
        float ra[NE];
#pragma unroll
        for (int e = 0; e < NE; e++) ra[e] = 0.f;
        for (int d = 0; d < DLS; d++) {
            float wv = g_wt_rk[d * DLS + c];
#pragma unroll
            for (int e = 0; e < NE; e++) ra[e] += s_s2[1 + e][d] * wv;
        }
        float rb = rkb[c], rqc = s_rq[c];
#pragma unroll
        for (int e = 0; e < NE; e++) s_red[e][c] = (ra[e] + rb) * rqc;
    }
    __syncthreads();

    // logits[e] = sum_c red[e][c] / sqrt(128)
    for (int e = w; e < NE; e += 4) {
        float s = s_red[e][lane] + s_red[e][lane + 32] + s_red[e][lane + 64] +
                  s_red[e][lane + 96];
#pragma unroll
        for (int o = 16; o > 0; o >>= 1) s += __shfl_down_sync(0xffffffffu, s, o);
        if (lane == 0) s_logit[e] = s * 0.08838834764831845f;  // 1/sqrt(128)
    }
    __syncthreads();

    if (c == 0) {
        float lg[NE], p[NE];
        float m = -1e30f;
#pragma unroll
        for (int e = 0; e < NE; e++) { lg[e] = s_logit[e]; m = fmaxf(m, lg[e]); }
        float sum = 0.f;
#pragma unroll
        for (int e = 0; e < NE; e++) { p[e] = expf(lg[e] - m); sum += p[e]; }
        float inv = 1.0f / sum;
#pragma unroll
        for (int e = 0; e < NE; e++) {
            p[e] *= inv;
            g_probs[n * NE + e] = p[e];
            s_coef[e] = 0.f;
        }
        // top-3 (ties -> lowest index, matching lax.top_k)
        int sel[3];
        float tw[3];
        bool used[NE] = {};
#pragma unroll
        for (int t = 0; t < 3; t++) {
            int bi = 0;
            float bv = -1.f;
#pragma unroll
            for (int e = 0; e < NE; e++)
                if (!used[e] && p[e] > bv) { bv = p[e]; bi = e; }
            used[bi] = true;
            sel[t] = bi;
            tw[t] = bv;
        }
        float tinv = 1.0f / (tw[0] + tw[1] + tw[2]);
#pragma unroll
        for (int t = 0; t < 3; t++) s_coef[sel[t]] = tw[t] * tinv;
#pragma unroll
        for (int e = 0; e < NE; e++) g_coef[n * NE + e] = s_coef[e];
    }
    __syncthreads();

    // Ahat = coef * gelu(ef)
#pragma unroll
    for (int e = 0; e < NE; e++) {
        float v = g_ef[(size_t)n * DIM + e * DLS + c];
        g_ahat[(size_t)n * DIM + e * DLS + c] = s_coef[e] * gelu_f(v);
    }
}

// ---------------- aux loss ---------------------------------------------------
__global__ void k_aux(float* __restrict__ out) {
    __shared__ float sp[256 * 8];
    __shared__ float sc2[256 * 8];
    int tid = threadIdx.x;
    float ps[NE], cs[NE];
#pragma unroll
    for (int e = 0; e < NE; e++) { ps[e] = 0.f; cs[e] = 0.f; }
    for (int nn = tid; nn < NTOK; nn += 256) {
#pragma unroll
        for (int e = 0; e < NE; e++) {
            ps[e] += g_probs[nn * NE + e];
            cs[e] += (g_coef[nn * NE + e] > 0.f) ? 1.0f : 0.0f;
        }
    }
#pragma unroll
    for (int e = 0; e < NE; e++) {
        sp[e * 256 + tid] = ps[e];
        sc2[e * 256 + tid] = cs[e];
    }
    __syncthreads();
    if (tid < NE) {
        float a = 0.f, bsum = 0.f;
        for (int i = 0; i < 256; i++) {
            a += sp[tid * 256 + i];
            bsum += sc2[tid * 256 + i];
        }
        sp[tid] = a;
        sc2[tid] = bsum;
    }
    __syncthreads();
    if (tid == 0) {
        float aux = 0.f;
        for (int e = 0; e < NE; e++)
            aux += (sp[e] * (1.0f / NTOK)) * (sc2[e] * (1.0f / NTOK));
        out[(size_t)NTOK * DIM] = 8.0f * aux;
    }
}

// ---------------- launch -----------------------------------------------------
extern "C" void kernel_launch(void* const* d_in, const int* in_sizes, int n_in,
                              void* d_out, int out_size) {
    const float* x    = (const float*)d_in[0];
    const float* wdn  = (const float*)d_in[1];
    const float* pos  = (const float*)d_in[2];
    const float* gpw  = (const float*)d_in[3];
    const float* gpb  = (const float*)d_in[4];
    const float* aiw  = (const float*)d_in[5];
    const float* aib  = (const float*)d_in[6];
    const float* aow  = (const float*)d_in[7];
    const float* aob  = (const float*)d_in[8];
    const float* nw   = (const float*)d_in[9];
    const float* nb   = (const float*)d_in[10];
    const float* rq1w = (const float*)d_in[11];
    const float* rq1b = (const float*)d_in[12];
    const float* rqlnw= (const float*)d_in[13];
    const float* rqlnb= (const float*)d_in[14];
    const float* rq2w = (const float*)d_in[15];
    const float* rq2b = (const float*)d_in[16];
    const float* rkw  = (const float*)d_in[17];
    const float* rkb  = (const float*)d_in[18];
    const float* wup  = (const float*)d_in[19];
    float* out = (float*)d_out;

    k_prep<<<320, 256>>>(aiw, aow, rkw);
    k_colmean<<<dim3(16, BBATCH), 256>>>(x);
    k_gemm_ef<<<dim3(8, 64), 256>>>(x, wdn);
    k_gctx_rq<<<BBATCH, 128>>>(gpw, gpb, rq1w, rq1b, rqlnw, rqlnb, rq2w, rq2b);
    k_token<<<NTOK, 128>>>(pos, aib, aob, nw, nb, rkb);
    k_gemm_out<<<dim3(8, 64), 256>>>(wup, out);
    k_aux<<<1, 256>>>(out);
}

// round 4
// speedup vs baseline: 1.0018x; 1.0018x over previous
#include <cuda_runtime.h>
#include <math.h>

#define NTOK 8192
#define DIM  1024
#define DLS  128
#define NE   8
#define NH   4
#define HDV  32
#define TT   2048
#define BBATCH 4
#define S9   9

// ---------------- scratch (device globals; no allocs allowed) ----------------
__device__ float g_ef[NTOK * DIM];      // expert_feats (N, E*DL)
__device__ float g_ahat[NTOK * DIM];    // coef * gelu(ef)
__device__ float g_xmean[BBATCH * DIM]; // sum over T (divide later)
__device__ float g_gctx[BBATCH * DLS];
__device__ float g_rq[BBATCH * DLS];
__device__ float g_probs[NTOK * NE];
__device__ float g_coef[NTOK * NE];
__device__ float g_wt_in[DLS * 384];    // attn_in_w transposed [d][j]
__device__ float g_wt_out[DLS * DLS];   // attn_out_w transposed
__device__ float g_wt_rk[DLS * DLS];    // rk_w transposed

__device__ __forceinline__ float gelu_f(float x) {
    return 0.5f * x * (1.0f + erff(x * 0.70710678118654752440f));
}

// ---------------- prep: zero accumulators + transpose small weights ----------
__global__ void k_prep(const float* __restrict__ aiw,
                       const float* __restrict__ aow,
                       const float* __restrict__ rkw) {
    int idx = blockIdx.x * blockDim.x + threadIdx.x;
    if (idx < BBATCH * DIM) g_xmean[idx] = 0.0f;
    if (idx < 384 * DLS) {
        int j = idx / DLS, d = idx % DLS;
        g_wt_in[d * 384 + j] = aiw[idx];
    } else if (idx < 384 * DLS + DLS * DLS) {
        int t = idx - 384 * DLS;
        int j = t / DLS, d = t % DLS;
        g_wt_out[d * DLS + j] = aow[t];
    } else if (idx < 384 * DLS + 2 * DLS * DLS) {
        int t = idx - 384 * DLS - DLS * DLS;
        int j = t / DLS, d = t % DLS;
        g_wt_rk[d * DLS + j] = rkw[t];
    }
}

// ---------------- column mean of x over T (partial sums via atomics) ---------
__global__ void k_colmean(const float* __restrict__ x) {
    int b = blockIdx.y, tc = blockIdx.x, tid = threadIdx.x;
    const float* xb = x + (size_t)b * TT * DIM + (size_t)tc * 128 * DIM;
    float acc[4] = {0.f, 0.f, 0.f, 0.f};
    for (int t = 0; t < 128; t++) {
        const float* row = xb + (size_t)t * DIM + tid;
#pragma unroll
        for (int i = 0; i < 4; i++) acc[i] += row[i * 256];
    }
#pragma unroll
    for (int i = 0; i < 4; i++)
        atomicAdd(&g_xmean[b * DIM + tid + i * 256], acc[i]);
}

// ---------------- block-wide sum over 128 threads ----------------------------
__device__ __forceinline__ float bsum128(float v, float* sred) {
    int tid = threadIdx.x;
#pragma unroll
    for (int o = 16; o > 0; o >>= 1) v += __shfl_down_sync(0xffffffffu, v, o);
    if ((tid & 31) == 0) sred[tid >> 5] = v;
    __syncthreads();
    float s = sred[0] + sred[1] + sred[2] + sred[3];
    __syncthreads();
    return s;
}

// ---------------- gctx + rq (per batch; grid=4, block=128) -------------------
__global__ void __launch_bounds__(128) k_gctx_rq(
    const float* __restrict__ gpw, const float* __restrict__ gpb,
    const float* __restrict__ rq1w, const float* __restrict__ rq1b,
    const float* __restrict__ rqlnw, const float* __restrict__ rqlnb,
    const float* __restrict__ rq2w, const float* __restrict__ rq2b) {
    __shared__ float sx[DIM];
    __shared__ float sg[DLS];
    __shared__ float sh[DLS];
    __shared__ float sred[4];
    int b = blockIdx.x, c = threadIdx.x;
    for (int i = c; i < DIM; i += 128) sx[i] = g_xmean[b * DIM + i] * (1.0f / TT);
    __syncthreads();

    // gctx[c] = sum_d xmean[d] * gpw[c][d] + gpb[c]
    float acc = 0.f;
    const float4* gw4 = (const float4*)(gpw + (size_t)c * DIM);
    const float4* sx4 = (const float4*)sx;
    for (int d4 = 0; d4 < DIM / 4; d4++) {
        float4 wv = gw4[d4], xv = sx4[d4];
        acc += wv.x * xv.x + wv.y * xv.y + wv.z * xv.z + wv.w * xv.w;
    }
    float gc = acc + gpb[c];
    g_gctx[b * DLS + c] = gc;
    sg[c] = gc;
    __syncthreads();

    // t = gctx @ rq1^T + b
    float t = 0.f;
    {
        const float4* w4 = (const float4*)(rq1w + (size_t)c * DLS);
        const float4* g4 = (const float4*)sg;
        for (int d4 = 0; d4 < DLS / 4; d4++) {
            float4 wv = w4[d4], xv = g4[d4];
            t += wv.x * xv.x + wv.y * xv.y + wv.z * xv.z + wv.w * xv.w;
        }
        t += rq1b[c];
    }
    // LN over 128
    float s = bsum128(t, sred);
    float q = bsum128(t * t, sred);
    float mu = s * (1.0f / 128.0f);
    float var = q * (1.0f / 128.0f) - mu * mu;
    float h = (t - mu) * rsqrtf(var + 1e-5f) * rqlnw[c] + rqlnb[c];
    h = gelu_f(h);
    sh[c] = h;
    __syncthreads();

    float r2 = 0.f;
    {
        const float4* w4 = (const float4*)(rq2w + (size_t)c * DLS);
        const float4* h4 = (const float4*)sh;
        for (int d4 = 0; d4 < DLS / 4; d4++) {
            float4 wv = w4[d4], xv = h4[d4];
            r2 += wv.x * xv.x + wv.y * xv.y + wv.z * xv.z + wv.w * xv.w;
        }
        r2 += rq2b[c];
    }
    g_rq[b * DLS + c] = r2;
}

// ---------------- tiled fp32 GEMM: C = A @ B^T (BT=1) or A @ B (BT=0) --------
template <bool BT>
__device__ __forceinline__ void gemm_dev(const float* __restrict__ A,
                                         const float* __restrict__ Bm,
                                         float* __restrict__ C,
                                         int M, int N, int Kd) {
    __shared__ __align__(16) float As[16][132];
    __shared__ __align__(16) float Bs[16][132];
    int tid = threadIdx.x;
    int tx = tid & 15, ty = tid >> 4;
    int n0 = blockIdx.x * 128, m0 = blockIdx.y * 128;
    float acc[8][8];
#pragma unroll
    for (int i = 0; i < 8; i++)
#pragma unroll
        for (int j = 0; j < 8; j++) acc[i][j] = 0.f;

    for (int k0 = 0; k0 < Kd; k0 += 16) {
#pragma unroll
        for (int i = 0; i < 8; i++) {
            int t = tid + i * 256;
            int r = t >> 4, k = t & 15;
            As[k][r] = A[(size_t)(m0 + r) * Kd + k0 + k];
        }
        if (BT) {
#pragma unroll
            for (int i = 0; i < 8; i++) {
                int t = tid + i * 256;
                int r = t >> 4, k = t & 15;
                Bs[k][r] = Bm[(size_t)(n0 + r) * Kd + k0 + k];
            }
        } else {
#pragma unroll
            for (int i = 0; i < 8; i++) {
                int t = tid + i * 256;
                int k = t >> 7, nn = t & 127;
                Bs[k][nn] = Bm[(size_t)(k0 + k) * N + n0 + nn];
            }
        }
        __syncthreads();
#pragma unroll
        for (int k = 0; k < 16; k++) {
            float4 a0 = *(const float4*)&As[k][ty * 8];
            float4 a1 = *(const float4*)&As[k][ty * 8 + 4];
            float4 b0 = *(const float4*)&Bs[k][tx * 8];
            float4 b1 = *(const float4*)&Bs[k][tx * 8 + 4];
            float av[8] = {a0.x, a0.y, a0.z, a0.w, a1.x, a1.y, a1.z, a1.w};
            float bv[8] = {b0.x, b0.y, b0.z, b0.w, b1.x, b1.y, b1.z, b1.w};
#pragma unroll
            for (int i = 0; i < 8; i++)
#pragma unroll
                for (int j = 0; j < 8; j++) acc[i][j] += av[i] * bv[j];
        }
        __syncthreads();
    }
#pragma unroll
    for (int i = 0; i < 8; i++) {
        float4 c0 = make_float4(acc[i][0], acc[i][1], acc[i][2], acc[i][3]);
        float4 c1 = make_float4(acc[i][4], acc[i][5], acc[i][6], acc[i][7]);
        size_t off = (size_t)(m0 + ty * 8 + i) * N + n0 + tx * 8;
        *(float4*)(C + off) = c0;
        *(float4*)(C + off + 4) = c1;
    }
}

__global__ void __launch_bounds__(256) k_gemm_ef(const float* __restrict__ A,
                                                const float* __restrict__ Bm) {
    gemm_dev<true>(A, Bm, g_ef, NTOK, DIM, DIM);
}
__global__ void __launch_bounds__(256) k_gemm_out(const float* __restrict__ Bm,
                                                 float* __restrict__ C) {
    gemm_dev<false>(g_ahat, Bm, C, NTOK, DIM, DIM);
}

// ---------------- per-token fused attention/router (grid=N, block=128) -------
__global__ void __launch_bounds__(128) k_token(
    const float* __restrict__ pos, const float* __restrict__ aib,
    const float* __restrict__ aob, const float* __restrict__ nw,
    const float* __restrict__ nb, const float* __restrict__ rkb) {
    __shared__ float s_seq[S9][DLS];
    __shared__ float s_qkv[S9][384];
    __shared__ float s_o[S9][DLS];
    __shared__ float s_s2[S9][DLS];
    __shared__ float s_red[NE][DLS];
    __shared__ float s_rq[DLS];
    __shared__ float s_mu[S9], s_rs[S9];
    __shared__ float s_logit[NE];
    __shared__ float s_coef[NE];

    int n = blockIdx.x;
    int b = n >> 11;  // T = 2048
    int c = threadIdx.x;
    int w = c >> 5, lane = c & 31;

    // build seq: row0 = gctx, rows 1..8 = ef + pos
    s_seq[0][c] = g_gctx[b * DLS + c];
#pragma unroll
    for (int e = 0; e < NE; e++)
        s_seq[1 + e][c] = g_ef[(size_t)n * DIM + e * DLS + c] + pos[e * DLS + c];
    s_rq[c] = g_rq[b * DLS + c];
    __syncthreads();

    // qkv = seq @ attn_in_w^T + b  (each thread owns cols c, c+128, c+256, all 9 rows)
    float acc0[S9], acc1[S9], acc2[S9];
#pragma unroll
    for (int r = 0; r < S9; r++) { acc0[r] = 0.f; acc1[r] = 0.f; acc2[r] = 0.f; }
    for (int d = 0; d < DLS; d++) {
        float w0 = g_wt_in[d * 384 + c];
        float w1 = g_wt_in[d * 384 + 128 + c];
        float w2 = g_wt_in[d * 384 + 256 + c];
#pragma unroll
        for (int r = 0; r < S9; r++) {
            float s = s_seq[r][d];
            acc0[r] += s * w0;
            acc1[r] += s * w1;
            acc2[r] += s * w2;
        }
    }
    {
        float b0 = aib[c], b1 = aib[128 + c], b2 = aib[256 + c];
#pragma unroll
        for (int r = 0; r < S9; r++) {
            s_qkv[r][c] = acc0[r] + b0;
            s_qkv[r][128 + c] = acc1[r] + b1;
            s_qkv[r][256 + c] = acc2[r] + b2;
        }
    }
    __syncthreads();

    // attention: warp w = head, lanes 0..8 = q rows
    if (lane < S9) {
        int h = w;
        const float scale = 0.17677669529663688f;  // 1/sqrt(32)
        float sc[S9];
#pragma unroll
        for (int j = 0; j < S9; j++) {
            float s = 0.f;
#pragma unroll
            for (int dd = 0; dd < HDV; dd++)
                s += s_qkv[lane][h * HDV + dd] * s_qkv[j][128 + h * HDV + dd];
            sc[j] = s * scale;
        }
        float m = sc[0];
#pragma unroll
        for (int j = 1; j < S9; j++) m = fmaxf(m, sc[j]);
        float ssum = 0.f;
#pragma unroll
        for (int j = 0; j < S9; j++) { sc[j] = expf(sc[j] - m); ssum += sc[j]; }
        float inv = 1.0f / ssum;
#pragma unroll
        for (int dd = 0; dd < HDV; dd++) {
            float o = 0.f;
#pragma unroll
            for (int j = 0; j < S9; j++) o += sc[j] * s_qkv[j][256 + h * HDV + dd];
            s_o[lane][h * HDV + dd] = o * inv;
        }
    }
    __syncthreads();

    // out proj + bias + residual
    {
        float po[S9];
#pragma unroll
        for (int r = 0; r < S9; r++) po[r] = 0.f;
        for (int d = 0; d < DLS; d++) {
            float wv = g_wt_out[d * DLS + c];
#pragma unroll
            for (int r = 0; r < S9; r++) po[r] += s_o[r][d] * wv;
        }
        float bo = aob[c];
#pragma unroll
        for (int r = 0; r < S9; r++) s_s2[r][c] = po[r] + bo + s_seq[r][c];
    }
    __syncthreads();

    // layernorm stats per row
    for (int r = w; r < S9; r += 4) {
        float v0 = s_s2[r][lane], v1 = s_s2[r][lane + 32];
        float v2 = s_s2[r][lane + 64], v3 = s_s2[r][lane + 96];
        float s = v0 + v1 + v2 + v3;
        float q = v0 * v0 + v1 * v1 + v2 * v2 + v3 * v3;
#pragma unroll
        for (int o = 16; o > 0; o >>= 1) {
            s += __shfl_down_sync(0xffffffffu, s, o);
            q += __shfl_down_sync(0xffffffffu, q, o);
        }
        if (lane == 0) {
            float mu = s * (1.0f / 128.0f);
            float var = q * (1.0f / 128.0f) - mu * mu;
            s_mu[r] = mu;
            s_rs[r] = rsqrtf(var + 1e-5f);
        }
    }
    __syncthreads();
    {
        float nwc = nw[c], nbc = nb[c];
#pragma unroll
        for (int r = 0; r < S9; r++) {
            float v = s_s2[r][c];
            s_s2[r][c] = (v - s_mu[r]) * s_rs[r] * nwc + nbc;
        }
    }
    __syncthreads();

    // rk = refined @ rk_w^T + b;  red[e][c] = rk[e][c] * rq[c]
    {
        float ra[NE];
#pragma unroll
        for (int e = 0; e < NE; e++) ra[e] = 0.f;
        for (int d = 0; d < DLS; d++) {
            float wv = g_wt_rk[d * DLS + c];
#pragma unroll
            for (int e = 0; e < NE; e++) ra[e] += s_s2[1 + e][d] * wv;
        }
        float rb = rkb[c], rqc = s_rq[c];
#pragma unroll
        for (int e = 0; e < NE; e++) s_red[e][c] = (ra[e] + rb) * rqc;
    }
    __syncthreads();

    // logits[e] = sum_c red[e][c] / sqrt(128)
    for (int e = w; e < NE; e += 4) {
        float s = s_red[e][lane] + s_red[e][lane + 32] + s_red[e][lane + 64] +
                  s_red[e][lane + 96];
#pragma unroll
        for (int o = 16; o > 0; o >>= 1) s += __shfl_down_sync(0xffffffffu, s, o);
        if (lane == 0) s_logit[e] = s * 0.08838834764831845f;  // 1/sqrt(128)
    }
    __syncthreads();

    if (c == 0) {
        float lg[NE], p[NE];
        float m = -1e30f;
#pragma unroll
        for (int e = 0; e < NE; e++) { lg[e] = s_logit[e]; m = fmaxf(m, lg[e]); }
        float sum = 0.f;
#pragma unroll
        for (int e = 0; e < NE; e++) { p[e] = expf(lg[e] - m); sum += p[e]; }
        float inv = 1.0f / sum;
#pragma unroll
        for (int e = 0; e < NE; e++) {
            p[e] *= inv;
            g_probs[n * NE + e] = p[e];
            s_coef[e] = 0.f;
        }
        // top-3 (ties -> lowest index, matching lax.top_k)
        int sel[3];
        float tw[3];
        bool used[NE] = {};
#pragma unroll
        for (int t = 0; t < 3; t++) {
            int bi = 0;
            float bv = -1.f;
#pragma unroll
            for (int e = 0; e < NE; e++)
                if (!used[e] && p[e] > bv) { bv = p[e]; bi = e; }
            used[bi] = true;
            sel[t] = bi;
            tw[t] = bv;
        }
        float tinv = 1.0f / (tw[0] + tw[1] + tw[2]);
#pragma unroll
        for (int t = 0; t < 3; t++) s_coef[sel[t]] = tw[t] * tinv;
#pragma unroll
        for (int e = 0; e < NE; e++) g_coef[n * NE + e] = s_coef[e];
    }
    __syncthreads();

    // Ahat = coef * gelu(ef)
#pragma unroll
    for (int e = 0; e < NE; e++) {
        float v = g_ef[(size_t)n * DIM + e * DLS + c];
        g_ahat[(size_t)n * DIM + e * DLS + c] = s_coef[e] * gelu_f(v);
    }
}

// ---------------- aux loss ---------------------------------------------------
__global__ void k_aux(float* __restrict__ out) {
    __shared__ float sp[256 * 8];
    __shared__ float sc2[256 * 8];
    int tid = threadIdx.x;
    float ps[NE], cs[NE];
#pragma unroll
    for (int e = 0; e < NE; e++) { ps[e] = 0.f; cs[e] = 0.f; }
    for (int nn = tid; nn < NTOK; nn += 256) {
#pragma unroll
        for (int e = 0; e < NE; e++) {
            ps[e] += g_probs[nn * NE + e];
            cs[e] += (g_coef[nn * NE + e] > 0.f) ? 1.0f : 0.0f;
        }
    }
#pragma unroll
    for (int e = 0; e < NE; e++) {
        sp[e * 256 + tid] = ps[e];
        sc2[e * 256 + tid] = cs[e];
    }
    __syncthreads();
    if (tid < NE) {
        float a = 0.f, bsum = 0.f;
        for (int i = 0; i < 256; i++) {
            a += sp[tid * 256 + i];
            bsum += sc2[tid * 256 + i];
        }
        sp[tid] = a;
        sc2[tid] = bsum;
    }
    __syncthreads();
    if (tid == 0) {
        float aux = 0.f;
        for (int e = 0; e < NE; e++)
            aux += (sp[e] * (1.0f / NTOK)) * (sc2[e] * (1.0f / NTOK));
        out[(size_t)NTOK * DIM] = 8.0f * aux;
    }
}

// ---------------- launch -----------------------------------------------------
extern "C" void kernel_launch(void* const* d_in, const int* in_sizes, int n_in,
                              void* d_out, int out_size) {
    const float* x    = (const float*)d_in[0];
    const float* wdn  = (const float*)d_in[1];
    const float* pos  = (const float*)d_in[2];
    const float* gpw  = (const float*)d_in[3];
    const float* gpb  = (const float*)d_in[4];
    const float* aiw  = (const float*)d_in[5];
    const float* aib  = (const float*)d_in[6];
    const float* aow  = (const float*)d_in[7];
    const float* aob  = (const float*)d_in[8];
    const float* nw   = (const float*)d_in[9];
    const float* nb   = (const float*)d_in[10];
    const float* rq1w = (const float*)d_in[11];
    const float* rq1b = (const float*)d_in[12];
    const float* rqlnw= (const float*)d_in[13];
    const float* rqlnb= (const float*)d_in[14];
    const float* rq2w = (const float*)d_in[15];
    const float* rq2b = (const float*)d_in[16];
    const float* rkw  = (const float*)d_in[17];
    const float* rkb  = (const float*)d_in[18];
    const float* wup  = (const float*)d_in[19];
    float* out = (float*)d_out;

    k_prep<<<320, 256>>>(aiw, aow, rkw);
    k_colmean<<<dim3(16, BBATCH), 256>>>(x);
    k_gemm_ef<<<dim3(8, 64), 256>>>(x, wdn);
    k_gctx_rq<<<BBATCH, 128>>>(gpw, gpb, rq1w, rq1b, rqlnw, rqlnb, rq2w, rq2b);
    k_token<<<NTOK, 128>>>(pos, aib, aob, nw, nb, rkb);
    k_gemm_out<<<dim3(8, 64), 256>>>(wup, out);
    k_aux<<<1, 256>>>(out);
}

// round 6
// speedup vs baseline: 1.5213x; 1.5186x over previous
#include <cuda_runtime.h>
#include <cuda_bf16.h>
#include <math.h>

#define NTOK 8192
#define DIM  1024
#define DLS  128
#define NE   8
#define HDV  32
#define TT   2048
#define BBATCH 4
#define S9   9

// ---------------- scratch ----------------------------------------------------
__device__ float g_ef[NTOK * DIM];
__device__ float g_xmean[BBATCH * DIM];
__device__ float g_gctx[BBATCH * DLS];
__device__ float g_rq[BBATCH * DLS];
__device__ float g_probs[NTOK * NE];
__device__ float g_coef[NTOK * NE];
__device__ float g_wt_in[DLS * 384];
__device__ float g_wt_out[DLS * DLS];
__device__ float g_wt_rk[DLS * DLS];

__device__ __align__(16) __nv_bfloat16 g_xh[NTOK * DIM];
__device__ __align__(16) __nv_bfloat16 g_xm[NTOK * DIM];
__device__ __align__(16) __nv_bfloat16 g_xl[NTOK * DIM];
__device__ __align__(16) __nv_bfloat16 g_w1h[DIM * DIM];
__device__ __align__(16) __nv_bfloat16 g_w1m[DIM * DIM];
__device__ __align__(16) __nv_bfloat16 g_w1l[DIM * DIM];
__device__ __align__(16) __nv_bfloat16 g_ah[NTOK * DIM];
__device__ __align__(16) __nv_bfloat16 g_al[NTOK * DIM];
__device__ __align__(16) __nv_bfloat16 g_w2h[DIM * DIM];
__device__ __align__(16) __nv_bfloat16 g_w2l[DIM * DIM];

__device__ __forceinline__ float gelu_f(float x) {
    return 0.5f * x * (1.0f + erff(x * 0.70710678118654752440f));
}

// ---------------- PTX helpers (target-portable: sm_80+) ----------------------
__device__ __forceinline__ unsigned smem_u32(const void* p) {
    unsigned a;
    asm("{ .reg .u64 t; cvta.to.shared.u64 t, %1; cvt.u32.u64 %0, t; }"
        : "=r"(a) : "l"(p));
    return a;
}
__device__ __forceinline__ void cp16(unsigned d, const void* g) {
    asm volatile("cp.async.cg.shared.global [%0], [%1], 16;" :: "r"(d), "l"(g));
}
__device__ __forceinline__ void ldm_x4(unsigned* r, unsigned addr) {
    asm volatile("ldmatrix.sync.aligned.m8n8.x4.shared.b16 {%0,%1,%2,%3}, [%4];"
                 : "=r"(r[0]), "=r"(r[1]), "=r"(r[2]), "=r"(r[3]) : "r"(addr));
}
__device__ __forceinline__ void mma16816(float* d, const unsigned* a,
                                         unsigned b0, unsigned b1) {
    asm volatile(
        "mma.sync.aligned.m16n8k16.row.col.f32.bf16.bf16.f32 "
        "{%0,%1,%2,%3}, {%4,%5,%6,%7}, {%8,%9}, {%0,%1,%2,%3};"
        : "+f"(d[0]), "+f"(d[1]), "+f"(d[2]), "+f"(d[3])
        : "r"(a[0]), "r"(a[1]), "r"(a[2]), "r"(a[3]), "r"(b0), "r"(b1));
}

// ---------------- HMMA GEMM: C[m][n] = sum over NP products A_p[m][:]*B_p[n][:]
// M=8192, N=1024, K=1024 per product. 128x128 tile, K-chunk 64 (128B rows,
// XOR-swizzled), 8 warps (2M x 4N), 2-stage cp.async pipeline.
template <int NP>
__device__ __forceinline__ void gemm_mma(
    const __nv_bfloat16* const* Al, const __nv_bfloat16* const* Bl,
    const signed char* pi, const signed char* pj, float* __restrict__ C) {
    extern __shared__ __align__(128) char smem[];
    int tid = threadIdx.x, lane = tid & 31, warp = tid >> 5;
    int n0 = blockIdx.x * 128, m0 = blockIdx.y * 128;
    int wm = (warp & 1) * 64, wn = (warp >> 1) * 32;
    unsigned sbase = smem_u32(smem);

    float acc[4][4][4] = {};

    auto load = [&](int t, int s) {
        const __nv_bfloat16* A = Al[pi[t >> 4]];
        const __nv_bfloat16* B = Bl[pj[t >> 4]];
        int k0 = (t & 15) * 64;
        unsigned sa = sbase + s * 32768u, sb = sa + 16384u;
#pragma unroll
        for (int i = 0; i < 4; i++) {
            int cid = tid + (i << 8);
            int r = cid >> 3, c = cid & 7;
            unsigned off = (unsigned)(r * 128 + ((c ^ (r & 7)) << 4));
            cp16(sa + off, (const char*)(A + (size_t)(m0 + r) * 1024 + k0) + c * 16);
            cp16(sb + off, (const char*)(B + (size_t)(n0 + r) * 1024 + k0) + c * 16);
        }
        asm volatile("cp.async.commit_group;" ::: "memory");
    };

    constexpr int T = NP * 16;
    load(0, 0);
#pragma unroll 1
    for (int t = 0; t < T; t++) {
        if (t + 1 < T) {
            load(t + 1, (t + 1) & 1);
            asm volatile("cp.async.wait_group 1;" ::: "memory");
        } else {
            asm volatile("cp.async.wait_group 0;" ::: "memory");
        }
        __syncthreads();
        unsigned sa = sbase + (unsigned)(t & 1) * 32768u, sb = sa + 16384u;
#pragma unroll
        for (int ks = 0; ks < 4; ks++) {
            int clo = ks * 2;
            unsigned a[4][4], b[2][4];
#pragma unroll
            for (int g = 0; g < 4; g++) {
                int row = wm + g * 16 + (lane & 15);
                int c = clo + (lane >> 4);
                ldm_x4(a[g], sa + row * 128 + ((c ^ (row & 7)) << 4));
            }
#pragma unroll
            for (int h = 0; h < 2; h++) {
                int row = wn + h * 16 + ((lane >> 4) << 3) + (lane & 7);
                int c = clo + ((lane >> 3) & 1);
                ldm_x4(b[h], sb + row * 128 + ((c ^ (row & 7)) << 4));
            }
#pragma unroll
            for (int i = 0; i < 4; i++)
#pragma unroll
                for (int j = 0; j < 4; j++) {
                    const unsigned* bf = &b[j >> 1][(j & 1) * 2];
                    mma16816(acc[i][j], a[i], bf[0], bf[1]);
                }
        }
        __syncthreads();
    }

#pragma unroll
    for (int i = 0; i < 4; i++) {
        int row = m0 + wm + i * 16 + (lane >> 2);
#pragma unroll
        for (int j = 0; j < 4; j++) {
            int col = n0 + wn + j * 8 + (lane & 3) * 2;
            *(float2*)(C + (size_t)row * 1024 + col) =
                make_float2(acc[i][j][0], acc[i][j][1]);
            *(float2*)(C + (size_t)(row + 8) * 1024 + col) =
                make_float2(acc[i][j][2], acc[i][j][3]);
        }
    }
}

__global__ void __launch_bounds__(256) k_gemm1() {
    const __nv_bfloat16* A[3] = {g_xh, g_xm, g_xl};
    const __nv_bfloat16* B[3] = {g_w1h, g_w1m, g_w1l};
    const signed char pi[6] = {0, 0, 1, 0, 1, 2};
    const signed char pj[6] = {0, 1, 0, 2, 1, 0};
    gemm_mma<6>(A, B, pi, pj, g_ef);
}
__global__ void __launch_bounds__(256) k_gemm2(float* __restrict__ C) {
    const __nv_bfloat16* A[2] = {g_ah, g_al};
    const __nv_bfloat16* B[2] = {g_w2h, g_w2l};
    const signed char pi[3] = {0, 0, 1};
    const signed char pj[3] = {0, 1, 0};
    gemm_mma<3>(A, B, pi, pj, C);
}

// ---------------- split kernels ----------------------------------------------
__device__ __forceinline__ unsigned pack2(__nv_bfloat16 a, __nv_bfloat16 b) {
    return (unsigned)__bfloat16_as_ushort(b) << 16 | __bfloat16_as_ushort(a);
}
__device__ __forceinline__ void split3_store(
    const float* __restrict__ src, __nv_bfloat16* dh, __nv_bfloat16* dm,
    __nv_bfloat16* dl, size_t i) {
    float4 v = ((const float4*)src)[i];
    float vs[4] = {v.x, v.y, v.z, v.w};
    __nv_bfloat16 h[4], m[4], l[4];
#pragma unroll
    for (int q = 0; q < 4; q++) {
        h[q] = __float2bfloat16(vs[q]);
        float r1 = vs[q] - __bfloat162float(h[q]);
        m[q] = __float2bfloat16(r1);
        l[q] = __float2bfloat16(r1 - __bfloat162float(m[q]));
    }
    ((uint2*)dh)[i] = make_uint2(pack2(h[0], h[1]), pack2(h[2], h[3]));
    ((uint2*)dm)[i] = make_uint2(pack2(m[0], m[1]), pack2(m[2], m[3]));
    ((uint2*)dl)[i] = make_uint2(pack2(l[0], l[1]), pack2(l[2], l[3]));
}
__global__ void k_split3_x(const float* __restrict__ x) {
    size_t i = (size_t)blockIdx.x * blockDim.x + threadIdx.x;
    split3_store(x, g_xh, g_xm, g_xl, i);
}
__global__ void k_split3_w(const float* __restrict__ w) {
    size_t i = (size_t)blockIdx.x * blockDim.x + threadIdx.x;
    split3_store(w, g_w1h, g_w1m, g_w1l, i);
}
__global__ void k_tsplit2_wup(const float* __restrict__ wup) {
    __shared__ float tile[32][33];
    int k0 = blockIdx.y * 32, m0 = blockIdx.x * 32;
    int tx = threadIdx.x, ty = threadIdx.y;
#pragma unroll
    for (int i = 0; i < 32; i += 8)
        tile[ty + i][tx] = wup[(size_t)(k0 + ty + i) * 1024 + m0 + tx];
    __syncthreads();
#pragma unroll
    for (int i = 0; i < 32; i += 8) {
        float v = tile[tx][ty + i];
        __nv_bfloat16 h = __float2bfloat16(v);
        size_t o = (size_t)(m0 + ty + i) * 1024 + k0 + tx;
        g_w2h[o] = h;
        g_w2l[o] = __float2bfloat16(v - __bfloat162float(h));
    }
}

// ---------------- prep -------------------------------------------------------
__global__ void k_prep(const float* __restrict__ aiw,
                       const float* __restrict__ aow,
                       const float* __restrict__ rkw) {
    int idx = blockIdx.x * blockDim.x + threadIdx.x;
    if (idx < BBATCH * DIM) g_xmean[idx] = 0.0f;
    if (idx < 384 * DLS) {
        int j = idx / DLS, d = idx % DLS;
        g_wt_in[d * 384 + j] = aiw[idx];
    } else if (idx < 384 * DLS + DLS * DLS) {
        int t = idx - 384 * DLS;
        g_wt_out[(t % DLS) * DLS + t / DLS] = aow[t];
    } else if (idx < 384 * DLS + 2 * DLS * DLS) {
        int t = idx - 384 * DLS - DLS * DLS;
        g_wt_rk[(t % DLS) * DLS + t / DLS] = rkw[t];
    }
}

__global__ void k_colmean(const float* __restrict__ x) {
    int b = blockIdx.y, tc = blockIdx.x, tid = threadIdx.x;
    const float* xb = x + (size_t)b * TT * DIM + (size_t)tc * 128 * DIM;
    float acc[4] = {0.f, 0.f, 0.f, 0.f};
    for (int t = 0; t < 128; t++) {
        const float* row = xb + (size_t)t * DIM + tid;
#pragma unroll
        for (int i = 0; i < 4; i++) acc[i] += row[i * 256];
    }
#pragma unroll
    for (int i = 0; i < 4; i++)
        atomicAdd(&g_xmean[b * DIM + tid + i * 256], acc[i]);
}

// ---------------- gctx + rq (grid=4, block=1024) -----------------------------
__global__ void __launch_bounds__(1024) k_gctx_rq2(
    const float* __restrict__ gpw, const float* __restrict__ gpb,
    const float* __restrict__ rq1w, const float* __restrict__ rq1b,
    const float* __restrict__ rqlnw, const float* __restrict__ rqlnb,
    const float* __restrict__ rq2w, const float* __restrict__ rq2b) {
    __shared__ float sx[DIM];
    __shared__ float sg[DLS], st[DLS], sh[DLS];
    __shared__ float sred[8];
    int b = blockIdx.x, t = threadIdx.x;
    sx[t] = g_xmean[b * DIM + t] * (1.0f / TT);
    __syncthreads();
    int c = t >> 3, seg = t & 7;
    {
        float acc = 0.f;
        const float4* w4 = (const float4*)(gpw + (size_t)c * DIM + seg * 128);
        const float4* x4 = (const float4*)(sx + seg * 128);
#pragma unroll 8
        for (int i = 0; i < 32; i++) {
            float4 w = w4[i], xx = x4[i];
            acc += w.x * xx.x + w.y * xx.y + w.z * xx.z + w.w * xx.w;
        }
        acc += __shfl_down_sync(0xffffffffu, acc, 4, 8);
        acc += __shfl_down_sync(0xffffffffu, acc, 2, 8);
        acc += __shfl_down_sync(0xffffffffu, acc, 1, 8);
        if (seg == 0) {
            float gc = acc + gpb[c];
            sg[c] = gc;
            g_gctx[b * DLS + c] = gc;
        }
    }
    __syncthreads();
    {
        float acc = 0.f;
        const float4* w4 = (const float4*)(rq1w + (size_t)c * DLS + seg * 16);
        const float4* x4 = (const float4*)(sg + seg * 16);
#pragma unroll
        for (int i = 0; i < 4; i++) {
            float4 w = w4[i], xx = x4[i];
            acc += w.x * xx.x + w.y * xx.y + w.z * xx.z + w.w * xx.w;
        }
        acc += __shfl_down_sync(0xffffffffu, acc, 4, 8);
        acc += __shfl_down_sync(0xffffffffu, acc, 2, 8);
        acc += __shfl_down_sync(0xffffffffu, acc, 1, 8);
        if (seg == 0) st[c] = acc + rq1b[c];
    }
    __syncthreads();
    if (t < DLS) {
        float v = st[t];
        float s = v, q = v * v;
#pragma unroll
        for (int o = 16; o > 0; o >>= 1) {
            s += __shfl_down_sync(0xffffffffu, s, o);
            q += __shfl_down_sync(0xffffffffu, q, o);
        }
        if ((t & 31) == 0) { sred[t >> 5] = s; sred[4 + (t >> 5)] = q; }
    }
    __syncthreads();
    if (t < DLS) {
        float s = sred[0] + sred[1] + sred[2] + sred[3];
        float q = sred[4] + sred[5] + sred[6] + sred[7];
        float mu = s * (1.0f / 128.0f);
        float var = q * (1.0f / 128.0f) - mu * mu;
        float h = (st[t] - mu) * rsqrtf(var + 1e-5f) * rqlnw[t] + rqlnb[t];
        sh[t] = gelu_f(h);
    }
    __syncthreads();
    {
        float acc = 0.f;
        const float4* w4 = (const float4*)(rq2w + (size_t)c * DLS + seg * 16);
        const float4* x4 = (const float4*)(sh + seg * 16);
#pragma unroll
        for (int i = 0; i < 4; i++) {
            float4 w = w4[i], xx = x4[i];
            acc += w.x * xx.x + w.y * xx.y + w.z * xx.z + w.w * xx.w;
        }
        acc += __shfl_down_sync(0xffffffffu, acc, 4, 8);
        acc += __shfl_down_sync(0xffffffffu, acc, 2, 8);
        acc += __shfl_down_sync(0xffffffffu, acc, 1, 8);
        if (seg == 0) g_rq[b * DLS + c] = acc + rq2b[c];
    }
}

// ---------------- per-token fused attention/router ---------------------------
__global__ void __launch_bounds__(128) k_token(
    const float* __restrict__ pos, const float* __restrict__ aib,
    const float* __restrict__ aob, const float* __restrict__ nw,
    const float* __restrict__ nb, const float* __restrict__ rkb) {
    __shared__ float s_seq[S9][DLS];
    __shared__ float s_qkv[S9][384];
    __shared__ float s_o[S9][DLS];
    __shared__ float s_s2[S9][DLS];
    __shared__ float s_red[NE][DLS];
    __shared__ float s_rq[DLS];
    __shared__ float s_mu[S9], s_rs[S9];
    __shared__ float s_logit[NE];
    __shared__ float s_coef[NE];

    int n = blockIdx.x;
    int b = n >> 11;
    int c = threadIdx.x;
    int w = c >> 5, lane = c & 31;

    s_seq[0][c] = g_gctx[b * DLS + c];
#pragma unroll
    for (int e = 0; e < NE; e++)
        s_seq[1 + e][c] = g_ef[(size_t)n * DIM + e * DLS + c] + pos[e * DLS + c];
    s_rq[c] = g_rq[b * DLS + c];
    __syncthreads();

    float acc0[S9], acc1[S9], acc2[S9];
#pragma unroll
    for (int r = 0; r < S9; r++) { acc0[r] = 0.f; acc1[r] = 0.f; acc2[r] = 0.f; }
    for (int d = 0; d < DLS; d++) {
        float w0 = g_wt_in[d * 384 + c];
        float w1 = g_wt_in[d * 384 + 128 + c];
        float w2 = g_wt_in[d * 384 + 256 + c];
#pragma unroll
        for (int r = 0; r < S9; r++) {
            float s = s_seq[r][d];
            acc0[r] += s * w0;
            acc1[r] += s * w1;
            acc2[r] += s * w2;
        }
    }
    {
        float b0 = aib[c], b1 = aib[128 + c], b2 = aib[256 + c];
#pragma unroll
        for (int r = 0; r < S9; r++) {
            s_qkv[r][c] = acc0[r] + b0;
            s_qkv[r][128 + c] = acc1[r] + b1;
            s_qkv[r][256 + c] = acc2[r] + b2;
        }
    }
    __syncthreads();

    if (lane < S9) {
        int h = w;
        const float scale = 0.17677669529663688f;
        float sc[S9];
#pragma unroll
        for (int j = 0; j < S9; j++) {
            float s = 0.f;
#pragma unroll
            for (int dd = 0; dd < HDV; dd++)
                s += s_qkv[lane][h * HDV + dd] * s_qkv[j][128 + h * HDV + dd];
            sc[j] = s * scale;
        }
        float m = sc[0];
#pragma unroll
        for (int j = 1; j < S9; j++) m = fmaxf(m, sc[j]);
        float ssum = 0.f;
#pragma unroll
        for (int j = 0; j < S9; j++) { sc[j] = expf(sc[j] - m); ssum += sc[j]; }
        float inv = 1.0f / ssum;
#pragma unroll
        for (int dd = 0; dd < HDV; dd++) {
            float o = 0.f;
#pragma unroll
            for (int j = 0; j < S9; j++) o += sc[j] * s_qkv[j][256 + h * HDV + dd];
            s_o[lane][h * HDV + dd] = o * inv;
        }
    }
    __syncthreads();

    {
        float po[S9];
#pragma unroll
        for (int r = 0; r < S9; r++) po[r] = 0.f;
        for (int d = 0; d < DLS; d++) {
            float wv = g_wt_out[d * DLS + c];
#pragma unroll
            for (int r = 0; r < S9; r++) po[r] += s_o[r][d] * wv;
        }
        float bo = aob[c];
#pragma unroll
        for (int r = 0; r < S9; r++) s_s2[r][c] = po[r] + bo + s_seq[r][c];
    }
    __syncthreads();

    for (int r = w; r < S9; r += 4) {
        float v0 = s_s2[r][lane], v1 = s_s2[r][lane + 32];
        float v2 = s_s2[r][lane + 64], v3 = s_s2[r][lane + 96];
        float s = v0 + v1 + v2 + v3;
        float q = v0 * v0 + v1 * v1 + v2 * v2 + v3 * v3;
#pragma unroll
        for (int o = 16; o > 0; o >>= 1) {
            s += __shfl_down_sync(0xffffffffu, s, o);
            q += __shfl_down_sync(0xffffffffu, q, o);
        }
        if (lane == 0) {
            float mu = s * (1.0f / 128.0f);
            float var = q * (1.0f / 128.0f) - mu * mu;
            s_mu[r] = mu;
            s_rs[r] = rsqrtf(var + 1e-5f);
        }
    }
    __syncthreads();
    {
        float nwc = nw[c], nbc = nb[c];
#pragma unroll
        for (int r = 0; r < S9; r++) {
            float v = s_s2[r][c];
            s_s2[r][c] = (v - s_mu[r]) * s_rs[r] * nwc + nbc;
        }
    }
    __syncthreads();

    {
        float ra[NE];
#pragma unroll
        for (int e = 0; e < NE; e++) ra[e] = 0.f;
        for (int d = 0; d < DLS; d++) {
            float wv = g_wt_rk[d * DLS + c];
#pragma unroll
            for (int e = 0; e < NE; e++) ra[e] += s_s2[1 + e][d] * wv;
        }
        float rb = rkb[c], rqc = s_rq[c];
#pragma unroll
        for (int e = 0; e < NE; e++) s_red[e][c] = (ra[e] + rb) * rqc;
    }
    __syncthreads();

    for (int e = w; e < NE; e += 4) {
        float s = s_red[e][lane] + s_red[e][lane + 32] + s_red[e][lane + 64] +
                  s_red[e][lane + 96];
#pragma unroll
        for (int o = 16; o > 0; o >>= 1) s += __shfl_down_sync(0xffffffffu, s, o);
        if (lane == 0) s_logit[e] = s * 0.08838834764831845f;
    }
    __syncthreads();

    if (c == 0) {
        float lg[NE], p[NE];
        float m = -1e30f;
#pragma unroll
        for (int e = 0; e < NE; e++) { lg[e] = s_logit[e]; m = fmaxf(m, lg[e]); }
        float sum = 0.f;
#pragma unroll
        for (int e = 0; e < NE; e++) { p[e] = expf(lg[e] - m); sum += p[e]; }
        float inv = 1.0f / sum;
#pragma unroll
        for (int e = 0; e < NE; e++) {
            p[e] *= inv;
            g_probs[n * NE + e] = p[e];
            s_coef[e] = 0.f;
        }
        int sel[3];
        float tw[3];
        bool used[NE] = {};
#pragma unroll
        for (int t = 0; t < 3; t++) {
            int bi = 0;
            float bv = -1.f;
#pragma unroll
            for (int e = 0; e < NE; e++)
                if (!used[e] && p[e] > bv) { bv = p[e]; bi = e; }
            used[bi] = true;
            sel[t] = bi;
            tw[t] = bv;
        }
        float tinv = 1.0f / (tw[0] + tw[1] + tw[2]);
#pragma unroll
        for (int t = 0; t < 3; t++) s_coef[sel[t]] = tw[t] * tinv;
#pragma unroll
        for (int e = 0; e < NE; e++) g_coef[n * NE + e] = s_coef[e];
    }
    __syncthreads();

    // Ahat = coef * gelu(ef) -> 2-way bf16 split
#pragma unroll
    for (int e = 0; e < NE; e++) {
        size_t idx = (size_t)n * DIM + e * DLS + c;
        float a = s_coef[e] * gelu_f(g_ef[idx]);
        __nv_bfloat16 h = __float2bfloat16(a);
        g_ah[idx] = h;
        g_al[idx] = __float2bfloat16(a - __bfloat162float(h));
    }
}

// ---------------- aux loss ---------------------------------------------------
__global__ void k_aux(float* __restrict__ out) {
    __shared__ float sp[256 * 8];
    __shared__ float sc2[256 * 8];
    int tid = threadIdx.x;
    float ps[NE], cs[NE];
#pragma unroll
    for (int e = 0; e < NE; e++) { ps[e] = 0.f; cs[e] = 0.f; }
    for (int nn = tid; nn < NTOK; nn += 256) {
#pragma unroll
        for (int e = 0; e < NE; e++) {
            ps[e] += g_probs[nn * NE + e];
            cs[e] += (g_coef[nn * NE + e] > 0.f) ? 1.0f : 0.0f;
        }
    }
#pragma unroll
    for (int e = 0; e < NE; e++) {
        sp[e * 256 + tid] = ps[e];
        sc2[e * 256 + tid] = cs[e];
    }
    __syncthreads();
    if (tid < NE) {
        float a = 0.f, bsum = 0.f;
        for (int i = 0; i < 256; i++) {
            a += sp[tid * 256 + i];
            bsum += sc2[tid * 256 + i];
        }
        sp[tid] = a;
        sc2[tid] = bsum;
    }
    __syncthreads();
    if (tid == 0) {
        float aux = 0.f;
        for (int e = 0; e < NE; e++)
            aux += (sp[e] * (1.0f / NTOK)) * (sc2[e] * (1.0f / NTOK));
        out[(size_t)NTOK * DIM] = 8.0f * aux;
    }
}

// ---------------- launch -----------------------------------------------------
extern "C" void kernel_launch(void* const* d_in, const int* in_sizes, int n_in,
                              void* d_out, int out_size) {
    const float* x    = (const float*)d_in[0];
    const float* wdn  = (const float*)d_in[1];
    const float* pos  = (const float*)d_in[2];
    const float* gpw  = (const float*)d_in[3];
    const float* gpb  = (const float*)d_in[4];
    const float* aiw  = (const float*)d_in[5];
    const float* aib  = (const float*)d_in[6];
    const float* aow  = (const float*)d_in[7];
    const float* aob  = (const float*)d_in[8];
    const float* nw   = (const float*)d_in[9];
    const float* nb   = (const float*)d_in[10];
    const float* rq1w = (const float*)d_in[11];
    const float* rq1b = (const float*)d_in[12];
    const float* rqlnw= (const float*)d_in[13];
    const float* rqlnb= (const float*)d_in[14];
    const float* rq2w = (const float*)d_in[15];
    const float* rq2b = (const float*)d_in[16];
    const float* rkw  = (const float*)d_in[17];
    const float* rkb  = (const float*)d_in[18];
    const float* wup  = (const float*)d_in[19];
    float* out = (float*)d_out;

    const int SMEM = 2 * 32768;  // 2 stages x (A 16KB + B 16KB)
    cudaFuncSetAttribute(k_gemm1, cudaFuncAttributeMaxDynamicSharedMemorySize, SMEM);
    cudaFuncSetAttribute(k_gemm2, cudaFuncAttributeMaxDynamicSharedMemorySize, SMEM);

    k_prep<<<320, 256>>>(aiw, aow, rkw);
    k_split3_x<<<8192, 256>>>(x);
    k_split3_w<<<1024, 256>>>(wdn);
    k_tsplit2_wup<<<dim3(32, 32), dim3(32, 8)>>>(wup);
    k_colmean<<<dim3(16, BBATCH), 256>>>(x);
    k_gemm1<<<dim3(8, 64), 256, SMEM>>>();
    k_gctx_rq2<<<BBATCH, 1024>>>(gpw, gpb, rq1w, rq1b, rqlnw, rqlnb, rq2w, rq2b);
    k_token<<<NTOK, 128>>>(pos, aib, aob, nw, nb, rkb);
    k_gemm2<<<dim3(8, 64), 256, SMEM>>>(out);
    k_aux<<<1, 256>>>(out);
}